// round 3
// baseline (speedup 1.0000x reference)
#include <cuda_runtime.h>
#include <cstdint>

#define NXDIM 512
#define NQDIM 128
#define NUDIM 64
#define BROWS 32768

// Scratch (allocation-free rule: __device__ globals)
__device__ float g_baseT[(size_t)NQDIM * BROWS];   // base transposed: [128][B]
__device__ float g_w[(size_t)BROWS * NQDIM];       // w row-major: [B][128]

// ---------------------------------------------------------------------------
// helpers
// ---------------------------------------------------------------------------
__device__ __forceinline__ uint32_t f2tf32(float f) {
    uint32_t r;
    asm("cvt.rna.tf32.f32 %0, %1;" : "=r"(r) : "f"(f));
    return r;
}

__device__ __forceinline__ float tanh_fast(float x) {
    float r;
    asm("tanh.approx.f32 %0, %1;" : "=f"(r) : "f"(x));
    return r;
}

__device__ __forceinline__ void mma_tf32(float c[4], const uint32_t a[4], const uint32_t b[2]) {
    asm volatile(
        "mma.sync.aligned.m16n8k8.row.col.f32.tf32.tf32.f32 "
        "{%0,%1,%2,%3}, {%4,%5,%6,%7}, {%8,%9}, {%0,%1,%2,%3};\n"
        : "+f"(c[0]), "+f"(c[1]), "+f"(c[2]), "+f"(c[3])
        : "r"(a[0]), "r"(a[1]), "r"(a[2]), "r"(a[3]), "r"(b[0]), "r"(b[1]));
}

__device__ __forceinline__ void ldsm_x4(uint32_t r[4], uint32_t addr) {
    asm volatile("ldmatrix.sync.aligned.m8n8.x4.shared.b16 {%0,%1,%2,%3}, [%4];"
                 : "=r"(r[0]), "=r"(r[1]), "=r"(r[2]), "=r"(r[3]) : "r"(addr));
}

// packed f32x2 (Blackwell)
__device__ __forceinline__ uint64_t pack2(float lo, float hi) {
    uint64_t r;
    asm("mov.b64 %0, {%1,%2};" : "=l"(r) : "f"(lo), "f"(hi));
    return r;
}
__device__ __forceinline__ void unpack2(float& lo, float& hi, uint64_t v) {
    asm("mov.b64 {%0,%1}, %2;" : "=f"(lo), "=f"(hi) : "l"(v));
}
__device__ __forceinline__ void ffma2(uint64_t& d, uint64_t a, uint64_t b) {
    asm("fma.rn.f32x2 %0, %1, %2, %0;" : "+l"(d) : "l"(a), "l"(b));
}

// ---------------------------------------------------------------------------
// Generic multi-segment GEMM: out[M,N] = sum_s Xs @ Ws^T + bias
//   Xs: [M, Ks] row-major, Ws: [N, Ks] row-major. Ks % 32 == 0.
//   transOut=0: out[m*N + n]; transOut=1: out[n*M + m]
// Block: 128(M) x 128(N) x 32(K), 256 threads (8 warps of 64x32),
// tf32 mma.sync m16n8k8, LDSM fragment loads, double-buffered smem,
// register-staged global->shared with cvt.rna.tf32.
// ---------------------------------------------------------------------------
#define GPAD 36
// dynamic smem layout (u32 units): A0=0, B0=4608, A1=9216, B1=13824 (each 128*36)
#define GEMM_SMEM_BYTES (4 * 128 * GPAD * 4)

__global__ void __launch_bounds__(256, 1) gemm_tf32_kernel(
    const float* __restrict__ X0, const float* __restrict__ W0, int K0,
    const float* __restrict__ X1, const float* __restrict__ W1, int K1,
    const float* __restrict__ X2, const float* __restrict__ W2, int K2,
    const float* __restrict__ bias, float* __restrict__ out,
    int N, int M, int transOut)
{
    extern __shared__ unsigned char smemraw[];
    uint32_t* sm = reinterpret_cast<uint32_t*>(smemraw);
    const uint32_t sbase = (uint32_t)__cvta_generic_to_shared(smemraw);

    const int tid  = threadIdx.x;
    const int bm   = blockIdx.x;
    const int bn   = blockIdx.y;
    const int lane = tid & 31;
    const int warp = tid >> 5;
    const int wm   = warp & 1;    // 0..1 -> 64-row slabs
    const int wn   = warp >> 1;   // 0..3 -> 32-col slabs
    const int qr   = lane >> 2;   // 0..7
    const int qc   = lane & 3;    // 0..3

    // per-lane LDSM base offsets (bytes)
    const int arow = wm * 64 + (lane & 8) + (lane & 7);
    const int acol = (lane & 16) ? 4 : 0;
    const uint32_t laneA = (uint32_t)((arow * GPAD + acol) * 4);
    const int brow = wn * 32 + ((lane & 16) >> 1) + (lane & 7);
    const int bcol = (lane & 8) ? 4 : 0;
    const uint32_t laneB = (uint32_t)((brow * GPAD + bcol) * 4);

    const int kt0 = K0 >> 5, kt1 = K1 >> 5, kt2 = K2 >> 5;
    const int ntiles = kt0 + kt1 + kt2;

    float acc[4][4][4];
#pragma unroll
    for (int i = 0; i < 4; i++)
#pragma unroll
        for (int j = 0; j < 4; j++)
#pragma unroll
            for (int k = 0; k < 4; k++) acc[i][j][k] = 0.f;

    float4 ra[4], rb[4];

    // ---- load tile 0 into registers ----
    {
        const float* xp; const float* wp_; int ld;
        if (kt0 > 0)      { xp = X0; wp_ = W0; ld = K0; }
        else if (kt1 > 0) { xp = X1; wp_ = W1; ld = K1; }
        else              { xp = X2; wp_ = W2; ld = K2; }
#pragma unroll
        for (int i = 0; i < 4; i++) {
            int idx = tid + i * 256;
            int row = idx >> 3;
            int c4  = (idx & 7) << 2;
            ra[i] = *reinterpret_cast<const float4*>(xp + (size_t)(bm * 128 + row) * ld + c4);
            rb[i] = *reinterpret_cast<const float4*>(wp_ + (size_t)(bn * 128 + row) * ld + c4);
        }
    }
    // ---- cvt + store tile 0 into buffer 0 ----
#pragma unroll
    for (int i = 0; i < 4; i++) {
        int idx = tid + i * 256;
        int row = idx >> 3;
        int c4  = (idx & 7) << 2;
        *reinterpret_cast<uint4*>(sm + row * GPAD + c4) =
            make_uint4(f2tf32(ra[i].x), f2tf32(ra[i].y), f2tf32(ra[i].z), f2tf32(ra[i].w));
        *reinterpret_cast<uint4*>(sm + 4608 + row * GPAD + c4) =
            make_uint4(f2tf32(rb[i].x), f2tf32(rb[i].y), f2tf32(rb[i].z), f2tf32(rb[i].w));
    }
    __syncthreads();

    for (int t = 0; t < ntiles; t++) {
        const int cur = t & 1;

        // ---- prefetch next tile into registers (overlaps mma) ----
        if (t + 1 < ntiles) {
            int tn = t + 1;
            const float* xp; const float* wp_; int ld, off;
            if (tn < kt0)            { xp = X0; wp_ = W0; ld = K0; off = tn << 5; }
            else if (tn < kt0 + kt1) { xp = X1; wp_ = W1; ld = K1; off = (tn - kt0) << 5; }
            else                     { xp = X2; wp_ = W2; ld = K2; off = (tn - kt0 - kt1) << 5; }
#pragma unroll
            for (int i = 0; i < 4; i++) {
                int idx = tid + i * 256;
                int row = idx >> 3;
                int c4  = (idx & 7) << 2;
                ra[i] = *reinterpret_cast<const float4*>(xp + (size_t)(bm * 128 + row) * ld + off + c4);
                rb[i] = *reinterpret_cast<const float4*>(wp_ + (size_t)(bn * 128 + row) * ld + off + c4);
            }
        }

        // ---- compute on buf[cur] ----
        const uint32_t aB = sbase + (cur ? 36864u : 0u);
        const uint32_t bB = sbase + (cur ? 55296u : 18432u);
#pragma unroll
        for (int kk = 0; kk < 4; kk++) {
            uint32_t afr[4][4];
            uint32_t bfr[2][4];
#pragma unroll
            for (int mt = 0; mt < 4; mt++)
                ldsm_x4(afr[mt], aB + laneA + (uint32_t)((mt * 16 * GPAD + kk * 8) * 4));
#pragma unroll
            for (int p = 0; p < 2; p++)
                ldsm_x4(bfr[p], bB + laneB + (uint32_t)((p * 16 * GPAD + kk * 8) * 4));
#pragma unroll
            for (int mt = 0; mt < 4; mt++) {
                mma_tf32(acc[mt][0], afr[mt], &bfr[0][0]);
                mma_tf32(acc[mt][1], afr[mt], &bfr[0][2]);
                mma_tf32(acc[mt][2], afr[mt], &bfr[1][0]);
                mma_tf32(acc[mt][3], afr[mt], &bfr[1][2]);
            }
        }

        // ---- cvt + store next tile into buf[1-cur] ----
        if (t + 1 < ntiles) {
            uint32_t* bufA = sm + (cur ? 0 : 9216);
            uint32_t* bufB = sm + (cur ? 4608 : 13824);
#pragma unroll
            for (int i = 0; i < 4; i++) {
                int idx = tid + i * 256;
                int row = idx >> 3;
                int c4  = (idx & 7) << 2;
                *reinterpret_cast<uint4*>(bufA + row * GPAD + c4) =
                    make_uint4(f2tf32(ra[i].x), f2tf32(ra[i].y), f2tf32(ra[i].z), f2tf32(ra[i].w));
                *reinterpret_cast<uint4*>(bufB + row * GPAD + c4) =
                    make_uint4(f2tf32(rb[i].x), f2tf32(rb[i].y), f2tf32(rb[i].z), f2tf32(rb[i].w));
            }
        }
        __syncthreads();
    }

    // ---- epilogue ----
#pragma unroll
    for (int mt = 0; mt < 4; mt++) {
#pragma unroll
        for (int nt = 0; nt < 4; nt++) {
            int m = bm * 128 + wm * 64 + mt * 16 + qr;
            int n = bn * 128 + wn * 32 + nt * 8 + 2 * qc;
            float b0 = __ldg(bias + n);
            float b1 = __ldg(bias + n + 1);
            float* c = acc[mt][nt];
            if (!transOut) {
                float2 v0 = make_float2(c[0] + b0, c[1] + b1);
                float2 v1 = make_float2(c[2] + b0, c[3] + b1);
                *reinterpret_cast<float2*>(out + (size_t)m * N + n)       = v0;
                *reinterpret_cast<float2*>(out + (size_t)(m + 8) * N + n) = v1;
            } else {
                out[(size_t)n * M + m]           = c[0] + b0;
                out[(size_t)(n + 1) * M + m]     = c[1] + b1;
                out[(size_t)n * M + m + 8]       = c[2] + b0;
                out[(size_t)(n + 1) * M + m + 8] = c[3] + b1;
            }
        }
    }
}

// ---------------------------------------------------------------------------
// Forward substitution: one thread per batch row, w[128] packed in 64 f32x2
// register pairs. D11 staged in 64KB shared (broadcast LDS.128, 2-cyc floor).
//   v_i = baseT[i][r] + sum_{j<i} w_j * D11[i][j];  w_i = tanh(v_i)
// Odd-i half-pair trick is exact: D11[i][i] == 0 and the unset hi lane is 0.0.
// ---------------------------------------------------------------------------
#define SUBST_SMEM_BYTES (NQDIM * NQDIM * 4)

__global__ void __launch_bounds__(256, 1) subst_kernel(
    const float* __restrict__ baseT, const float* __restrict__ D11,
    float* __restrict__ w_out, int Bn)
{
    extern __shared__ unsigned char sraw[];
    float* sD = reinterpret_cast<float*>(sraw);

    // stage D11 into shared
    {
        float4* dst = reinterpret_cast<float4*>(sD);
        const float4* src = reinterpret_cast<const float4*>(D11);
        for (int k = threadIdx.x; k < NQDIM * NQDIM / 4; k += 256)
            dst[k] = src[k];
    }
    __syncthreads();

    const int r = blockIdx.x * 256 + threadIdx.x;

    uint64_t wp[NQDIM / 2];
#pragma unroll
    for (int p = 0; p < NQDIM / 2; p++) wp[p] = 0ull;
    float wlast = 0.f;

#pragma unroll
    for (int i = 0; i < NQDIM; i++) {
        const float bse = __ldg(baseT + (size_t)i * Bn + r);
        uint64_t va = 0ull, vc = 0ull;
        const int np = (i + 1) >> 1;  // pairs covering cols 0..i (diag is 0)
        const ulonglong2* dp = reinterpret_cast<const ulonglong2*>(sD + i * NQDIM);
#pragma unroll
        for (int t = 0; t < (np >> 1); t++) {
            ulonglong2 dd = dp[t];
            ffma2(va, wp[2 * t],     dd.x);
            ffma2(vc, wp[2 * t + 1], dd.y);
        }
        if (np & 1) {
            uint64_t d1 = reinterpret_cast<const unsigned long long*>(dp)[np - 1];
            ffma2(va, wp[np - 1], d1);
        }
        float a0, a1, c0, c1;
        unpack2(a0, a1, va);
        unpack2(c0, c1, vc);
        float wi = tanh_fast(bse + ((a0 + a1) + (c0 + c1)));
        if ((i & 1) == 0) { wp[i >> 1] = pack2(wi, 0.f); wlast = wi; }
        else              { wp[i >> 1] = pack2(wlast, wi); }
    }

    float4* wo = reinterpret_cast<float4*>(w_out + (size_t)r * NQDIM);
#pragma unroll
    for (int p = 0; p < NQDIM / 4; p++) {
        float x0, x1, x2, x3;
        unpack2(x0, x1, wp[2 * p]);
        unpack2(x2, x3, wp[2 * p + 1]);
        wo[p] = make_float4(x0, x1, x2, x3);
    }
}

// ---------------------------------------------------------------------------
// launch
// ---------------------------------------------------------------------------
extern "C" void kernel_launch(void* const* d_in, const int* in_sizes, int n_in,
                              void* d_out, int out_size)
{
    const float* xi  = (const float*)d_in[0];
    const float* u   = (const float*)d_in[1];
    const float* A   = (const float*)d_in[2];
    const float* B1  = (const float*)d_in[3];
    const float* B2  = (const float*)d_in[4];
    const float* C1  = (const float*)d_in[5];
    const float* D11 = (const float*)d_in[6];
    const float* D12 = (const float*)d_in[7];
    const float* bx  = (const float*)d_in[8];
    const float* bv  = (const float*)d_in[9];
    float* out = (float*)d_out;

    const int Bn = in_sizes[0] / NXDIM;  // 32768

    void* pBaseT = nullptr;
    void* pW     = nullptr;
    cudaGetSymbolAddress(&pBaseT, g_baseT);
    cudaGetSymbolAddress(&pW, g_w);
    float* baseT = (float*)pBaseT;
    float* w     = (float*)pW;

    static bool attr_done = false;
    if (!attr_done) {
        cudaFuncSetAttribute(gemm_tf32_kernel,
                             cudaFuncAttributeMaxDynamicSharedMemorySize, GEMM_SMEM_BYTES);
        cudaFuncSetAttribute(subst_kernel,
                             cudaFuncAttributeMaxDynamicSharedMemorySize, SUBST_SMEM_BYTES);
        attr_done = true;
    }

    dim3 blk(256);

    // base^T = ([xi|u] @ [C1|D12]^T + bv)^T     -> [128, B]
    gemm_tf32_kernel<<<dim3(Bn / 128, 1), blk, GEMM_SMEM_BYTES>>>(
        xi, C1, NXDIM, u, D12, NUDIM, nullptr, nullptr, 0,
        bv, baseT, NQDIM, Bn, 1);

    // forward substitution -> w [B, 128]
    subst_kernel<<<Bn / 256, 256, SUBST_SMEM_BYTES>>>(baseT, D11, w, Bn);

    // out = xi@A^T + w@B1^T + u@B2^T + bx       -> [B, 512]
    gemm_tf32_kernel<<<dim3(Bn / 128, 4), blk, GEMM_SMEM_BYTES>>>(
        xi, A, NXDIM, w, B1, NQDIM, u, B2, NUDIM,
        bx, out, NXDIM, Bn, 0);
}

// round 5
// speedup vs baseline: 2.0945x; 2.0945x over previous
#include <cuda_runtime.h>
#include <cuda_fp16.h>
#include <cstdint>

#define BN_ALL 32768
#define ACT_LD 704   // [xi(512) | w(128) | u(64)]

// device scratch (allocation-free rule)
__device__ __half g_act[(size_t)BN_ALL * ACT_LD];
__device__ __half g_W3[512 * ACT_LD];    // [512][A|B1|B2]
__device__ __half g_W1[128 * 576];       // [128][C1|D12]
__device__ float  g_baseT[(size_t)128 * BN_ALL];

// ---------------- helpers ----------------
__device__ __forceinline__ float tanh_fast(float x){ float r; asm("tanh.approx.f32 %0,%1;":"=f"(r):"f"(x)); return r; }
__device__ __forceinline__ uint64_t pack2(float lo, float hi){ uint64_t r; asm("mov.b64 %0,{%1,%2};":"=l"(r):"f"(lo),"f"(hi)); return r; }
__device__ __forceinline__ void unpack2(float& lo, float& hi, uint64_t v){ asm("mov.b64 {%0,%1},%2;":"=f"(lo),"=f"(hi):"l"(v)); }
__device__ __forceinline__ void ffma2(uint64_t& d, uint64_t a, uint64_t b){ asm("fma.rn.f32x2 %0,%1,%2,%0;":"+l"(d):"l"(a),"l"(b)); }
__device__ __forceinline__ void cp16(uint32_t d, const void* s){ asm volatile("cp.async.cg.shared.global [%0],[%1],16;"::"r"(d),"l"(s):"memory"); }
__device__ __forceinline__ void ldsm4(uint32_t r[4], uint32_t a){
    asm volatile("ldmatrix.sync.aligned.m8n8.x4.shared.b16 {%0,%1,%2,%3},[%4];"
                 : "=r"(r[0]),"=r"(r[1]),"=r"(r[2]),"=r"(r[3]) : "r"(a));
}
__device__ __forceinline__ void mma_f16(float c[4], const uint32_t a[4], const uint32_t b0, const uint32_t b1){
    asm volatile("mma.sync.aligned.m16n8k16.row.col.f32.f16.f16.f32 "
                 "{%0,%1,%2,%3},{%4,%5,%6,%7},{%8,%9},{%0,%1,%2,%3};"
                 : "+f"(c[0]),"+f"(c[1]),"+f"(c[2]),"+f"(c[3])
                 : "r"(a[0]),"r"(a[1]),"r"(a[2]),"r"(a[3]),"r"(b0),"r"(b1));
}

// ---------------- prepass: fp32 -> fp16 (xi, u, W3=[A|B1|B2], W1=[C1|D12]) ----------------
#define XIU 2097152L
#define UU  262144L
#define W3U 45056L
#define W1U 9216L
__global__ void __launch_bounds__(256) prep_kernel(
    const float* __restrict__ xi, const float* __restrict__ u,
    const float* __restrict__ A, const float* __restrict__ B1,
    const float* __restrict__ B2, const float* __restrict__ C1,
    const float* __restrict__ D12)
{
    long unit = (long)blockIdx.x * 256 + threadIdx.x;
    const float* src; __half* dst;
    if (unit < XIU){
        long e = unit * 8; long row = e >> 9; int col = (int)(e & 511);
        src = xi + e; dst = g_act + row * ACT_LD + col;
    } else if (unit < XIU + UU){
        long e = (unit - XIU) * 8; long row = e >> 6; int col = (int)(e & 63);
        src = u + e; dst = g_act + row * ACT_LD + 640 + col;
    } else if (unit < XIU + UU + W3U){
        long e = (unit - XIU - UU) * 8; int n = (int)(e / ACT_LD), k = (int)(e % ACT_LD);
        src = (k < 512) ? A + n*512 + k : (k < 640 ? B1 + n*128 + (k-512) : B2 + n*64 + (k-640));
        dst = g_W3 + (size_t)n * ACT_LD + k;
    } else if (unit < XIU + UU + W3U + W1U){
        long e = (unit - XIU - UU - W3U) * 8; int n = (int)(e / 576), k = (int)(e % 576);
        src = (k < 512) ? C1 + n*512 + k : D12 + n*64 + (k-512);
        dst = g_W1 + (size_t)n * 576 + k;
    } else return;
    float4 v0 = *reinterpret_cast<const float4*>(src);
    float4 v1 = *reinterpret_cast<const float4*>(src + 4);
    __half2 h0 = __floats2half2_rn(v0.x, v0.y), h1 = __floats2half2_rn(v0.z, v0.w);
    __half2 h2 = __floats2half2_rn(v1.x, v1.y), h3 = __floats2half2_rn(v1.z, v1.w);
    uint4 o; o.x = *reinterpret_cast<uint32_t*>(&h0); o.y = *reinterpret_cast<uint32_t*>(&h1);
    o.z = *reinterpret_cast<uint32_t*>(&h2); o.w = *reinterpret_cast<uint32_t*>(&h3);
    *reinterpret_cast<uint4*>(dst) = o;
}

// ---------------- fp16 GEMM: out[M,N(grid)] = act @ W^T + bias ----------------
// BM=128, BN=128, BK=64 fp16; 256 thr, 8 warps (64x32 each); cp.async double buffer.
// smem: A0@0, A1@16K, B0@32K, B1@48K  (row = 128B, XOR-16B swizzle)
#define GH_SMEM 65536
__global__ void __launch_bounds__(256,2) gemm_h_kernel(
    const __half* __restrict__ act, int aLD,
    const __half* __restrict__ W, int wLD,
    int ntiles, int g1flag,
    const float* __restrict__ bias, float* __restrict__ out,
    int N, int M, int transOut)
{
    extern __shared__ unsigned char smem[];
    const uint32_t s = (uint32_t)__cvta_generic_to_shared(smem);
    const int tid = threadIdx.x, lane = tid & 31, warp = tid >> 5;
    const int mb = blockIdx.x, bn = blockIdx.y;
    const int wm = warp & 1, wn = warp >> 1;
    const int qr = lane >> 2, qc = lane & 3;

    // ldmatrix lane mapping (canonical m16n8k16)
    const int a_r = lane & 15, a_c = lane >> 4;                    // A: rows 0-15 x2 chunks
    const int b_r = (lane & 7) + ((lane & 16) >> 1);               // B: n-rows
    const int b_c = (lane >> 3) & 1;

    float acc[4][4][4];
#pragma unroll
    for (int i=0;i<4;i++)
#pragma unroll
        for (int j=0;j<4;j++)
#pragma unroll
            for (int k=0;k<4;k++) acc[i][j][k]=0.f;

    // tile loader
    auto issue = [&](int t, int b){
        const int koffA = g1flag ? (t < 8 ? t*64 : 640) : t*64;
        const int koffW = t * 64;
        const uint32_t Ab = s + b*16384, Bb = s + 32768 + b*16384;
#pragma unroll
        for (int i=0;i<4;i++){
            int idx = tid + i*256, row = idx >> 3, kc = idx & 7;
            cp16(Ab + row*128 + ((kc ^ (row & 7)) << 4),
                 act + (size_t)(mb*128 + row)*aLD + koffA + kc*8);
            cp16(Bb + row*128 + ((kc ^ (row & 7)) << 4),
                 W + (size_t)(bn*128 + row)*wLD + koffW + kc*8);
        }
        asm volatile("cp.async.commit_group;" ::: "memory");
    };

    issue(0, 0);
    for (int t = 0; t < ntiles; t++){
        const int b = t & 1;
        if (t + 1 < ntiles){
            issue(t + 1, 1 - b);
            asm volatile("cp.async.wait_group 1;" ::: "memory");
        } else {
            asm volatile("cp.async.wait_group 0;" ::: "memory");
        }
        __syncthreads();

        const uint32_t Ab = s + b*16384, Bb = s + 32768 + b*16384;
#pragma unroll
        for (int kk = 0; kk < 4; kk++){
            uint32_t afr[4][4], bfr[2][4];
#pragma unroll
            for (int mt = 0; mt < 4; mt++){
                int row = wm*64 + mt*16 + a_r;
                int ch = (2*kk + a_c) ^ (row & 7);
                ldsm4(afr[mt], Ab + row*128 + (ch << 4));
            }
#pragma unroll
            for (int nb = 0; nb < 2; nb++){
                int row = wn*32 + nb*16 + b_r;
                int ch = (2*kk + b_c) ^ (row & 7);
                ldsm4(bfr[nb], Bb + row*128 + (ch << 4));
            }
#pragma unroll
            for (int mt = 0; mt < 4; mt++){
                mma_f16(acc[mt][0], afr[mt], bfr[0][0], bfr[0][1]);
                mma_f16(acc[mt][1], afr[mt], bfr[0][2], bfr[0][3]);
                mma_f16(acc[mt][2], afr[mt], bfr[1][0], bfr[1][1]);
                mma_f16(acc[mt][3], afr[mt], bfr[1][2], bfr[1][3]);
            }
        }
        __syncthreads();
    }

    // epilogue (same fragment layout as m16n8k8: c0,c1 @ row qr col 2qc; c2,c3 @ row+8)
#pragma unroll
    for (int mt = 0; mt < 4; mt++){
#pragma unroll
        for (int nt = 0; nt < 4; nt++){
            int m = mb*128 + wm*64 + mt*16 + qr;
            int n = bn*128 + wn*32 + nt*8 + 2*qc;
            float b0 = __ldg(bias + n), b1 = __ldg(bias + n + 1);
            float* c = acc[mt][nt];
            if (!transOut){
                *reinterpret_cast<float2*>(out + (size_t)m*N + n)       = make_float2(c[0]+b0, c[1]+b1);
                *reinterpret_cast<float2*>(out + (size_t)(m+8)*N + n)   = make_float2(c[2]+b0, c[3]+b1);
            } else {
                out[(size_t)n*M + m]         = c[0]+b0;
                out[(size_t)(n+1)*M + m]     = c[1]+b1;
                out[(size_t)n*M + m + 8]     = c[2]+b0;
                out[(size_t)(n+1)*M + m + 8] = c[3]+b1;
            }
        }
    }
}

// ---------------- subst: w_i = tanh(base_i + sum_{j<i} w_j D11[i][j]) -> fp16 into act ----------------
#define SUBST_SMEM (128*128*4)
__global__ void __launch_bounds__(128,2) subst_kernel(const float* __restrict__ D11){
    extern __shared__ unsigned char sraw[];
    float* sD = reinterpret_cast<float*>(sraw);
    {
        float4* dst = reinterpret_cast<float4*>(sD);
        const float4* src = reinterpret_cast<const float4*>(D11);
        for (int k = threadIdx.x; k < 128*128/4; k += 128) dst[k] = src[k];
    }
    __syncthreads();
    const int r = blockIdx.x*128 + threadIdx.x;
    uint64_t wp[64];
#pragma unroll
    for (int p=0;p<64;p++) wp[p]=0ull;
    float wlast = 0.f;
#pragma unroll
    for (int i=0;i<128;i++){
        const float bse = __ldg(g_baseT + (size_t)i*BN_ALL + r);
        uint64_t va=0ull, vc=0ull;
        const int np = (i+1)>>1;
        const ulonglong2* dp = reinterpret_cast<const ulonglong2*>(sD + i*128);
#pragma unroll
        for (int q=0;q<(np>>1);q++){
            ulonglong2 dd = dp[q];
            ffma2(va, wp[2*q], dd.x);
            ffma2(vc, wp[2*q+1], dd.y);
        }
        if (np & 1){
            uint64_t d1 = reinterpret_cast<const unsigned long long*>(dp)[np-1];
            ffma2(va, wp[np-1], d1);
        }
        float a0,a1,c0,c1; unpack2(a0,a1,va); unpack2(c0,c1,vc);
        float wi = tanh_fast(bse + ((a0+a1)+(c0+c1)));
        if ((i&1)==0){ wp[i>>1] = pack2(wi, 0.f); wlast = wi; }
        else         { wp[i>>1] = pack2(wlast, wi); }
    }
    uint4* dst = reinterpret_cast<uint4*>(g_act + (size_t)r*ACT_LD + 512);
#pragma unroll
    for (int q=0;q<16;q++){
        float a0,a1,b0,b1,c0,c1,d0,d1;
        unpack2(a0,a1,wp[4*q]);   unpack2(b0,b1,wp[4*q+1]);
        unpack2(c0,c1,wp[4*q+2]); unpack2(d0,d1,wp[4*q+3]);
        __half2 ha=__floats2half2_rn(a0,a1), hb=__floats2half2_rn(b0,b1);
        __half2 hc=__floats2half2_rn(c0,c1), hd=__floats2half2_rn(d0,d1);
        uint4 v; v.x=*reinterpret_cast<uint32_t*>(&ha); v.y=*reinterpret_cast<uint32_t*>(&hb);
        v.z=*reinterpret_cast<uint32_t*>(&hc); v.w=*reinterpret_cast<uint32_t*>(&hd);
        dst[q] = v;
    }
}

// ---------------- launch ----------------
extern "C" void kernel_launch(void* const* d_in, const int* in_sizes, int n_in,
                              void* d_out, int out_size)
{
    const float* xi  = (const float*)d_in[0];
    const float* u   = (const float*)d_in[1];
    const float* A   = (const float*)d_in[2];
    const float* B1  = (const float*)d_in[3];
    const float* B2  = (const float*)d_in[4];
    const float* C1  = (const float*)d_in[5];
    const float* D11 = (const float*)d_in[6];
    const float* D12 = (const float*)d_in[7];
    const float* bx  = (const float*)d_in[8];
    const float* bv  = (const float*)d_in[9];
    float* out = (float*)d_out;

    void* pBaseT = nullptr; cudaGetSymbolAddress(&pBaseT, g_baseT);
    void* pAct   = nullptr; cudaGetSymbolAddress(&pAct,   g_act);
    void* pW3    = nullptr; cudaGetSymbolAddress(&pW3,    g_W3);
    void* pW1    = nullptr; cudaGetSymbolAddress(&pW1,    g_W1);

    static bool attr_done = false;
    if (!attr_done){
        cudaFuncSetAttribute(gemm_h_kernel, cudaFuncAttributeMaxDynamicSharedMemorySize, GH_SMEM);
        cudaFuncSetAttribute(subst_kernel,  cudaFuncAttributeMaxDynamicSharedMemorySize, SUBST_SMEM);
        attr_done = true;
    }

    const long total_units = XIU + UU + W3U + W1U;
    prep_kernel<<<(unsigned)((total_units + 255) / 256), 256>>>(xi, u, A, B1, B2, C1, D12);

    // GEMM1: baseT = ([xi|u] @ [C1|D12]^T + bv)^T   [128][B]
    gemm_h_kernel<<<dim3(BN_ALL/128, 1), 256, GH_SMEM>>>(
        (const __half*)pAct, ACT_LD, (const __half*)pW1, 576, 9, 1,
        bv, (float*)pBaseT, 128, BN_ALL, 1);

    // subst -> w fp16 into act[:,512:640)
    subst_kernel<<<BN_ALL/128, 128, SUBST_SMEM>>>(D11);

    // GEMM3: out = act @ [A|B1|B2]^T + bx   [B][512]
    gemm_h_kernel<<<dim3(BN_ALL/128, 4), 256, GH_SMEM>>>(
        (const __half*)pAct, ACT_LD, (const __half*)pW3, ACT_LD, 11, 0,
        bx, out, 512, BN_ALL, 0);
}

// round 6
// speedup vs baseline: 2.1489x; 1.0260x over previous
#include <cuda_runtime.h>
#include <cuda_fp16.h>
#include <cstdint>

#define BN_ALL 32768
#define ACT_LD 704   // [xi(512) | w(128) | u(64)]

// device scratch (allocation-free rule)
__device__ __half g_act[(size_t)BN_ALL * ACT_LD];
__device__ __half g_W3[512 * ACT_LD];    // [512][A|B1|B2]
__device__ __half g_W1[128 * 576];       // [128][C1|D12]
__device__ float  g_baseT[(size_t)128 * BN_ALL];

// ---------------- helpers ----------------
__device__ __forceinline__ float tanh_fast(float x){ float r; asm("tanh.approx.f32 %0,%1;":"=f"(r):"f"(x)); return r; }
__device__ __forceinline__ uint64_t pack2(float lo, float hi){ uint64_t r; asm("mov.b64 %0,{%1,%2};":"=l"(r):"f"(lo),"f"(hi)); return r; }
__device__ __forceinline__ void unpack2(float& lo, float& hi, uint64_t v){ asm("mov.b64 {%0,%1},%2;":"=f"(lo),"=f"(hi):"l"(v)); }
__device__ __forceinline__ void ffma2(uint64_t& d, uint64_t a, uint64_t b){ asm("fma.rn.f32x2 %0,%1,%2,%0;":"+l"(d):"l"(a),"l"(b)); }
__device__ __forceinline__ void cp16(uint32_t d, const void* s){ asm volatile("cp.async.cg.shared.global [%0],[%1],16;"::"r"(d),"l"(s):"memory"); }
__device__ __forceinline__ void ldsm4(uint32_t r[4], uint32_t a){
    asm volatile("ldmatrix.sync.aligned.m8n8.x4.shared.b16 {%0,%1,%2,%3},[%4];"
                 : "=r"(r[0]),"=r"(r[1]),"=r"(r[2]),"=r"(r[3]) : "r"(a));
}
__device__ __forceinline__ void mma_f16(float c[4], const uint32_t a[4], const uint32_t b0, const uint32_t b1){
    asm volatile("mma.sync.aligned.m16n8k16.row.col.f32.f16.f16.f32 "
                 "{%0,%1,%2,%3},{%4,%5,%6,%7},{%8,%9},{%0,%1,%2,%3};"
                 : "+f"(c[0]),"+f"(c[1]),"+f"(c[2]),"+f"(c[3])
                 : "r"(a[0]),"r"(a[1]),"r"(a[2]),"r"(a[3]),"r"(b0),"r"(b1));
}

// ---------------- prepass: fp32 -> fp16 (xi, u, W3=[A|B1|B2], W1=[C1|D12]) ----------------
#define XIU 2097152L
#define UU  262144L
#define W3U 45056L
#define W1U 9216L
__global__ void __launch_bounds__(256) prep_kernel(
    const float* __restrict__ xi, const float* __restrict__ u,
    const float* __restrict__ A, const float* __restrict__ B1,
    const float* __restrict__ B2, const float* __restrict__ C1,
    const float* __restrict__ D12)
{
    long unit = (long)blockIdx.x * 256 + threadIdx.x;
    const float* src; __half* dst;
    if (unit < XIU){
        long e = unit * 8; long row = e >> 9; int col = (int)(e & 511);
        src = xi + e; dst = g_act + row * ACT_LD + col;
    } else if (unit < XIU + UU){
        long e = (unit - XIU) * 8; long row = e >> 6; int col = (int)(e & 63);
        src = u + e; dst = g_act + row * ACT_LD + 640 + col;
    } else if (unit < XIU + UU + W3U){
        long e = (unit - XIU - UU) * 8; int n = (int)(e / ACT_LD), k = (int)(e % ACT_LD);
        src = (k < 512) ? A + n*512 + k : (k < 640 ? B1 + n*128 + (k-512) : B2 + n*64 + (k-640));
        dst = g_W3 + (size_t)n * ACT_LD + k;
    } else if (unit < XIU + UU + W3U + W1U){
        long e = (unit - XIU - UU - W3U) * 8; int n = (int)(e / 576), k = (int)(e % 576);
        src = (k < 512) ? C1 + n*512 + k : D12 + n*64 + (k-512);
        dst = g_W1 + (size_t)n * 576 + k;
    } else return;
    float4 v0 = *reinterpret_cast<const float4*>(src);
    float4 v1 = *reinterpret_cast<const float4*>(src + 4);
    __half2 h0 = __floats2half2_rn(v0.x, v0.y), h1 = __floats2half2_rn(v0.z, v0.w);
    __half2 h2 = __floats2half2_rn(v1.x, v1.y), h3 = __floats2half2_rn(v1.z, v1.w);
    uint4 o; o.x = *reinterpret_cast<uint32_t*>(&h0); o.y = *reinterpret_cast<uint32_t*>(&h1);
    o.z = *reinterpret_cast<uint32_t*>(&h2); o.w = *reinterpret_cast<uint32_t*>(&h3);
    *reinterpret_cast<uint4*>(dst) = o;
}

// ---------------- fp16 GEMM: out[M,N] = act @ W^T + bias ----------------
// BM=128, BN=128, BK=64 fp16; 256 thr, 8 warps (64x32 each).
// Ring-3 cp.async pipeline, ONE __syncthreads per K-tile.
// smem: A_i @ i*16K (i=0..2), B_i @ 48K + i*16K. Row = 128B, XOR-16B swizzle.
#define GH_SMEM 98304
__global__ void __launch_bounds__(256,2) gemm_h_kernel(
    const __half* __restrict__ act, int aLD,
    const __half* __restrict__ W, int wLD,
    int ntiles, int g1flag,
    const float* __restrict__ bias, float* __restrict__ out,
    int N, int M, int transOut)
{
    extern __shared__ unsigned char smem[];
    const uint32_t s = (uint32_t)__cvta_generic_to_shared(smem);
    const int tid = threadIdx.x, lane = tid & 31, warp = tid >> 5;
    const int bn = blockIdx.x, mb = blockIdx.y;   // bn fastest: act rows shared by consecutive CTAs
    const int wm = warp & 1, wn = warp >> 1;
    const int qr = lane >> 2, qc = lane & 3;

    // ldmatrix lane mapping (canonical m16n8k16)
    const int a_r = lane & 15, a_c = lane >> 4;
    const int b_r = (lane & 7) + ((lane & 16) >> 1);
    const int b_c = (lane >> 3) & 1;

    float acc[4][4][4];
#pragma unroll
    for (int i=0;i<4;i++)
#pragma unroll
        for (int j=0;j<4;j++)
#pragma unroll
            for (int k=0;k<4;k++) acc[i][j][k]=0.f;

    auto issue = [&](int t, int b){
        const int koffA = g1flag ? (t < 8 ? t*64 : 640) : t*64;
        const int koffW = t * 64;
        const uint32_t Ab = s + b*16384, Bb = s + 49152 + b*16384;
#pragma unroll
        for (int i=0;i<4;i++){
            int idx = tid + i*256, row = idx >> 3, kc = idx & 7;
            cp16(Ab + row*128 + ((kc ^ (row & 7)) << 4),
                 act + (size_t)(mb*128 + row)*aLD + koffA + kc*8);
            cp16(Bb + row*128 + ((kc ^ (row & 7)) << 4),
                 W + (size_t)(bn*128 + row)*wLD + koffW + kc*8);
        }
        asm volatile("cp.async.commit_group;" ::: "memory");
    };

    issue(0, 0);
    issue(1, 1);
    for (int t = 0; t < ntiles; t++){
        if (t + 1 < ntiles) asm volatile("cp.async.wait_group 1;" ::: "memory");
        else                asm volatile("cp.async.wait_group 0;" ::: "memory");
        __syncthreads();

        const int b = t % 3;
        const uint32_t Ab = s + b*16384, Bb = s + 49152 + b*16384;
#pragma unroll
        for (int kk = 0; kk < 4; kk++){
            uint32_t afr[4][4], bfr[2][4];
#pragma unroll
            for (int mt = 0; mt < 4; mt++){
                int row = wm*64 + mt*16 + a_r;
                int ch = (2*kk + a_c) ^ (row & 7);
                ldsm4(afr[mt], Ab + row*128 + (ch << 4));
            }
#pragma unroll
            for (int nb = 0; nb < 2; nb++){
                int row = wn*32 + nb*16 + b_r;
                int ch = (2*kk + b_c) ^ (row & 7);
                ldsm4(bfr[nb], Bb + row*128 + (ch << 4));
            }
#pragma unroll
            for (int mt = 0; mt < 4; mt++){
                mma_f16(acc[mt][0], afr[mt], bfr[0][0], bfr[0][1]);
                mma_f16(acc[mt][1], afr[mt], bfr[0][2], bfr[0][3]);
                mma_f16(acc[mt][2], afr[mt], bfr[1][0], bfr[1][1]);
                mma_f16(acc[mt][3], afr[mt], bfr[1][2], bfr[1][3]);
            }
        }
        if (t + 2 < ntiles) issue(t + 2, (t + 2) % 3);
    }

    // epilogue (fragment layout: c0,c1 @ row qr col 2qc; c2,c3 @ row+8)
#pragma unroll
    for (int mt = 0; mt < 4; mt++){
#pragma unroll
        for (int nt = 0; nt < 4; nt++){
            int m = mb*128 + wm*64 + mt*16 + qr;
            int n = bn*128 + wn*32 + nt*8 + 2*qc;
            float b0 = __ldg(bias + n), b1 = __ldg(bias + n + 1);
            float* c = acc[mt][nt];
            if (!transOut){
                *reinterpret_cast<float2*>(out + (size_t)m*N + n)     = make_float2(c[0]+b0, c[1]+b1);
                *reinterpret_cast<float2*>(out + (size_t)(m+8)*N + n) = make_float2(c[2]+b0, c[3]+b1);
            } else {
                out[(size_t)n*M + m]         = c[0]+b0;
                out[(size_t)(n+1)*M + m]     = c[1]+b1;
                out[(size_t)n*M + m + 8]     = c[2]+b0;
                out[(size_t)(n+1)*M + m + 8] = c[3]+b1;
            }
        }
    }
}

// ---------------- subst: w_i = tanh(base_i + sum_{j<i} w_j D11[i][j]) -> fp16 into act ----------------
#define SUBST_SMEM (128*128*4)
__global__ void __launch_bounds__(128,2) subst_kernel(const float* __restrict__ D11){
    extern __shared__ unsigned char sraw[];
    float* sD = reinterpret_cast<float*>(sraw);
    {
        float4* dst = reinterpret_cast<float4*>(sD);
        const float4* src = reinterpret_cast<const float4*>(D11);
        for (int k = threadIdx.x; k < 128*128/4; k += 128) dst[k] = src[k];
    }
    __syncthreads();
    const int r = blockIdx.x*128 + threadIdx.x;
    uint64_t wp[64];
#pragma unroll
    for (int p=0;p<64;p++) wp[p]=0ull;
    float wlast = 0.f;
#pragma unroll
    for (int i=0;i<128;i++){
        const float bse = __ldg(g_baseT + (size_t)i*BN_ALL + r);
        uint64_t va=0ull, vc=0ull;
        const int np = (i+1)>>1;
        const ulonglong2* dp = reinterpret_cast<const ulonglong2*>(sD + i*128);
#pragma unroll
        for (int q=0;q<(np>>1);q++){
            ulonglong2 dd = dp[q];
            ffma2(va, wp[2*q], dd.x);
            ffma2(vc, wp[2*q+1], dd.y);
        }
        if (np & 1){
            uint64_t d1 = reinterpret_cast<const unsigned long long*>(dp)[np-1];
            ffma2(va, wp[np-1], d1);
        }
        float a0,a1,c0,c1; unpack2(a0,a1,va); unpack2(c0,c1,vc);
        float wi = tanh_fast(bse + ((a0+a1)+(c0+c1)));
        if ((i&1)==0){ wp[i>>1] = pack2(wi, 0.f); wlast = wi; }
        else         { wp[i>>1] = pack2(wlast, wi); }
    }
    uint4* dst = reinterpret_cast<uint4*>(g_act + (size_t)r*ACT_LD + 512);
#pragma unroll
    for (int q=0;q<16;q++){
        float a0,a1,b0,b1,c0,c1,d0,d1;
        unpack2(a0,a1,wp[4*q]);   unpack2(b0,b1,wp[4*q+1]);
        unpack2(c0,c1,wp[4*q+2]); unpack2(d0,d1,wp[4*q+3]);
        __half2 ha=__floats2half2_rn(a0,a1), hb=__floats2half2_rn(b0,b1);
        __half2 hc=__floats2half2_rn(c0,c1), hd=__floats2half2_rn(d0,d1);
        uint4 v; v.x=*reinterpret_cast<uint32_t*>(&ha); v.y=*reinterpret_cast<uint32_t*>(&hb);
        v.z=*reinterpret_cast<uint32_t*>(&hc); v.w=*reinterpret_cast<uint32_t*>(&hd);
        dst[q] = v;
    }
}

// ---------------- launch ----------------
extern "C" void kernel_launch(void* const* d_in, const int* in_sizes, int n_in,
                              void* d_out, int out_size)
{
    const float* xi  = (const float*)d_in[0];
    const float* u   = (const float*)d_in[1];
    const float* A   = (const float*)d_in[2];
    const float* B1  = (const float*)d_in[3];
    const float* B2  = (const float*)d_in[4];
    const float* C1  = (const float*)d_in[5];
    const float* D11 = (const float*)d_in[6];
    const float* D12 = (const float*)d_in[7];
    const float* bx  = (const float*)d_in[8];
    const float* bv  = (const float*)d_in[9];
    float* out = (float*)d_out;

    void* pBaseT = nullptr; cudaGetSymbolAddress(&pBaseT, g_baseT);
    void* pAct   = nullptr; cudaGetSymbolAddress(&pAct,   g_act);
    void* pW3    = nullptr; cudaGetSymbolAddress(&pW3,    g_W3);
    void* pW1    = nullptr; cudaGetSymbolAddress(&pW1,    g_W1);

    static bool attr_done = false;
    if (!attr_done){
        cudaFuncSetAttribute(gemm_h_kernel, cudaFuncAttributeMaxDynamicSharedMemorySize, GH_SMEM);
        cudaFuncSetAttribute(subst_kernel,  cudaFuncAttributeMaxDynamicSharedMemorySize, SUBST_SMEM);
        attr_done = true;
    }

    const long total_units = XIU + UU + W3U + W1U;
    prep_kernel<<<(unsigned)((total_units + 255) / 256), 256>>>(xi, u, A, B1, B2, C1, D12);

    // GEMM1: baseT = ([xi|u] @ [C1|D12]^T + bv)^T   [128][B]
    gemm_h_kernel<<<dim3(1, BN_ALL/128), 256, GH_SMEM>>>(
        (const __half*)pAct, ACT_LD, (const __half*)pW1, 576, 9, 1,
        bv, (float*)pBaseT, 128, BN_ALL, 1);

    // subst -> w fp16 into act[:,512:640)
    subst_kernel<<<BN_ALL/128, 128, SUBST_SMEM>>>(D11);

    // GEMM3: out = act @ [A|B1|B2]^T + bx   [B][512]
    gemm_h_kernel<<<dim3(4, BN_ALL/128), 256, GH_SMEM>>>(
        (const __half*)pAct, ACT_LD, (const __half*)pW3, ACT_LD, 11, 0,
        bx, out, 512, BN_ALL, 0);
}